// round 3
// baseline (speedup 1.0000x reference)
#include <cuda_runtime.h>
#include <cuda_bf16.h>

#define BATCH 8
#define CC    64
#define DD    8
#define NPIX  4096

// ---------------- device scratch (no cudaMalloc allowed) ----------------
__device__ float g_Q[BATCH * NPIX * DD];    // [b][n][d]   1 MB
__device__ float g_K[BATCH * NPIX * DD];    // [b][m][d]   1 MB
__device__ float g_V[BATCH * NPIX * CC];    // [b][m][c]   8 MB
__device__ float g_Zp[4 * BATCH * NPIX];    // [split][b][m] partial Z sums

typedef unsigned long long u64;

__device__ __forceinline__ void ffma2(u64 &d, u64 a, u64 b) {
    asm("fma.rn.f32x2 %0, %1, %2, %0;" : "+l"(d) : "l"(a), "l"(b));
}
__device__ __forceinline__ u64 pack2(float lo, float hi) {
    u64 r; asm("mov.b64 %0, {%1, %2};" : "=l"(r) : "f"(lo), "f"(hi)); return r;
}
__device__ __forceinline__ float2 unpack2(u64 v) {
    float lo, hi; asm("mov.b64 {%0, %1}, %2;" : "=f"(lo), "=f"(hi) : "l"(v));
    return make_float2(lo, hi);
}

// ---------------- 1: per-pixel projections (1x1 convs) ----------------
__global__ void __launch_bounds__(256) proj_kernel(
    const float* __restrict__ x,
    const float* __restrict__ Wq, const float* __restrict__ bq,
    const float* __restrict__ Wk, const float* __restrict__ bk,
    const float* __restrict__ Wv, const float* __restrict__ bv)
{
    __shared__ float sWqT[CC * DD];   // [c][d]
    __shared__ float sWkT[CC * DD];   // [c][d]
    __shared__ float sWvT[CC * CC];   // [c][d_out]
    const int tid = threadIdx.x;
    const int b = blockIdx.y;
    const int n = blockIdx.x * 256 + tid;

    for (int i = tid; i < CC * DD; i += 256) {
        int d = i >> 6, c = i & 63;
        sWqT[c * DD + d] = Wq[i];
        sWkT[c * DD + d] = Wk[i];
    }
    for (int i = tid; i < CC * CC; i += 256) {
        int d = i >> 6, c = i & 63;
        sWvT[c * CC + d] = Wv[i];
    }
    __syncthreads();

    float q[DD], k[DD], v[CC];
#pragma unroll
    for (int d = 0; d < DD; d++) { q[d] = 0.f; k[d] = 0.f; }
#pragma unroll
    for (int d = 0; d < CC; d++) v[d] = 0.f;

    const float* xp = x + (b * CC) * NPIX + n;
#pragma unroll 1
    for (int c = 0; c < CC; c++) {
        float xc = xp[c * NPIX];                  // coalesced across threads
        const float* wq = sWqT + c * DD;
        const float* wk = sWkT + c * DD;
        const float* wv = sWvT + c * CC;
#pragma unroll
        for (int d = 0; d < DD; d++) {
            q[d] = fmaf(wq[d], xc, q[d]);
            k[d] = fmaf(wk[d], xc, k[d]);
        }
#pragma unroll
        for (int d = 0; d < CC; d++) v[d] = fmaf(wv[d], xc, v[d]);
    }

    float* qo = g_Q + ((b << 12) + n) * DD;
    float* ko = g_K + ((b << 12) + n) * DD;
#pragma unroll
    for (int d = 0; d < DD; d++) {
        qo[d] = q[d] + __ldg(bq + d);
        ko[d] = k[d] + __ldg(bk + d);
    }
    float* vo = g_V + ((b << 12) + n) * CC;
#pragma unroll
    for (int d = 0; d < CC; d++) vo[d] = v[d] + __ldg(bv + d);
}

// ---------------- 2: column sums Z[m] = sum_n exp(s[n,m]) ----------------
__global__ void __launch_bounds__(128) zr_kernel()
{
    const int tid = threadIdx.x;
    const int b = blockIdx.z;
    const int ns = blockIdx.y;
    const int m = blockIdx.x * 128 + tid;

    const float4* kp = (const float4*)(g_K + ((b << 12) + m) * DD);
    const float4 ka = kp[0], kb = kp[1];

    __shared__ float4 sQ[256];   // 128 query vectors
    float z0 = 0.f, z1 = 0.f;

    for (int t = 0; t < 8; t++) {
        const int nb = ns * 1024 + t * 128;
        __syncthreads();
        const float4* qg = (const float4*)(g_Q + ((b << 12) + nb) * DD);
        sQ[tid] = qg[tid];
        sQ[tid + 128] = qg[tid + 128];
        __syncthreads();
#pragma unroll 4
        for (int nl = 0; nl < 128; nl += 2) {
            float4 qa = sQ[nl * 2],     qb = sQ[nl * 2 + 1];
            float4 qc = sQ[nl * 2 + 2], qd = sQ[nl * 2 + 3];
            float s0 = ka.x*qa.x + ka.y*qa.y + ka.z*qa.z + ka.w*qa.w
                     + kb.x*qb.x + kb.y*qb.y + kb.z*qb.z + kb.w*qb.w;
            float s1 = ka.x*qc.x + ka.y*qc.y + ka.z*qc.z + ka.w*qc.w
                     + kb.x*qd.x + kb.y*qd.y + kb.z*qd.z + kb.w*qd.w;
            z0 += __expf(s0 * 0.125f);
            z1 += __expf(s1 * 0.125f);
        }
    }
    g_Zp[(ns * BATCH + b) * NPIX + m] = z0 + z1;
}

// ---------------- 3: fused out[c,n] = sum_m (V[c,m]/Z[m]) * exp(s[n,m]) ----------------
// grid (32 n-tiles, B), 256 threads, single m pass (64 tiles of 64).
// smem bytes: sVdup u64[64*64]=32768 | sP f32[64*128]=32768 | sQ f32[1024]=4096
//           | sK f32[512]=2048 | sRz f32[64]=256  -> 70192 B
#define OFF_VDUP 0
#define OFF_P    32768
#define OFF_Q    (32768 + 32768)
#define OFF_K    (OFF_Q + 4096)
#define OFF_RZ   (OFF_K + 2048)
#define OUT_SMEM (OFF_RZ + 256)

__global__ void __launch_bounds__(256, 2) out_kernel(float* __restrict__ out)
{
    extern __shared__ char smraw[];
    u64*   sVdup = (u64*)(smraw + OFF_VDUP);      // [m][c] duplicated (v,v)
    float* sP    = (float*)(smraw + OFF_P);       // [m][n] exp scores
    float* sQ    = (float*)(smraw + OFF_Q);       // [n][d]
    float* sK    = (float*)(smraw + OFF_K);       // [m][d]
    float* sRz   = (float*)(smraw + OFF_RZ);      // [m] 1/Z

    const int tid = threadIdx.x;
    const int b  = blockIdx.y;
    const int n_base = blockIdx.x * 128;

    // load 128 query vectors once
    const float4* qg = (const float4*)(g_Q + ((b << 12) + n_base) * DD);
    ((float4*)sQ)[tid] = qg[tid];

    u64 acc[16];
#pragma unroll
    for (int i = 0; i < 16; i++) acc[i] = 0ULL;

    const int c0 = (tid >> 4) * 4;     // phase-B c group (4)
    const int n0 = (tid & 15) * 8;     // phase-B n group (8 = 4 pairs)
    const int am0 = (tid >> 4) * 4;    // phase-A m group (4)
    const int an0 = (tid & 15) * 8;    // phase-A n group (8)

    for (int mt = 0; mt < 64; mt++) {
        const int m_base = mt * 64;
        __syncthreads();   // prev phase B done reading sVdup/sP; sQ ready on iter 0

        // segment 1: load K tile + reciprocal Z
        if (tid < 128)
            ((float4*)sK)[tid] =
                ((const float4*)(g_K + ((b << 12) + m_base) * DD))[tid];
        if (tid < 64) {
            const int m = m_base + tid;
            float z = g_Zp[(0 * BATCH + b) * NPIX + m]
                    + g_Zp[(1 * BATCH + b) * NPIX + m]
                    + g_Zp[(2 * BATCH + b) * NPIX + m]
                    + g_Zp[(3 * BATCH + b) * NPIX + m];
            sRz[tid] = 1.0f / z;
        }
        __syncthreads();

        // segment 2a: load V tile scaled by 1/Z, store duplicated (v,v) pairs
        const float4* vg = (const float4*)(g_V + ((b << 12) + m_base) * CC);
#pragma unroll
        for (int kk = 0; kk < 4; kk++) {
            int j = kk * 256 + tid;        // 1024 float4s = [64][16 float4]
            float4 t = vg[j];
            float r = sRz[j >> 4];
            t.x *= r; t.y *= r; t.z *= r; t.w *= r;
            ulonglong2* dst = (ulonglong2*)(sVdup + j * 4);
            ulonglong2 d0, d1;
            d0.x = pack2(t.x, t.x); d0.y = pack2(t.y, t.y);
            d1.x = pack2(t.z, t.z); d1.y = pack2(t.w, t.w);
            dst[0] = d0;
            dst[1] = d1;
        }

        // segment 2b: phase A — scores + exp into sP[m][n]
        // q vectors cached in registers across the mi loop (half of 8 n's at a time)
#pragma unroll
        for (int half = 0; half < 2; half++) {
            const int na = an0 + half * 4;
            float4 qa[4], qb[4];
#pragma unroll
            for (int j = 0; j < 4; j++) {
                qa[j] = *(const float4*)(sQ + (na + j) * 8);
                qb[j] = *(const float4*)(sQ + (na + j) * 8 + 4);
            }
#pragma unroll
            for (int mi = 0; mi < 4; mi++) {
                const int m = am0 + mi;
                const float4 ka = *(const float4*)(sK + m * 8);
                const float4 kb = *(const float4*)(sK + m * 8 + 4);
                float e[4];
#pragma unroll
                for (int j = 0; j < 4; j++) {
                    float s = ka.x*qa[j].x + ka.y*qa[j].y + ka.z*qa[j].z + ka.w*qa[j].w
                            + kb.x*qb[j].x + kb.y*qb[j].y + kb.z*qb[j].z + kb.w*qb[j].w;
                    e[j] = __expf(s * 0.125f);
                }
                *(float4*)(sP + m * 128 + na) = make_float4(e[0], e[1], e[2], e[3]);
            }
        }
        __syncthreads();

        // segment 3: phase B — rank-1 accumulate, all operands native 64-bit from smem
#pragma unroll 4
        for (int m = 0; m < 64; m++) {
            const u64* vrow = sVdup + m * 64;
            ulonglong2 va01 = *(const ulonglong2*)(vrow + c0);       // (v0,v0),(v1,v1)
            ulonglong2 va23 = *(const ulonglong2*)(vrow + c0 + 2);   // (v2,v2),(v3,v3)
            const u64* prow = (const u64*)(sP + m * 128) + (n0 >> 1);
            ulonglong2 pA = *(const ulonglong2*)(prow);              // pairs n0..n0+3
            ulonglong2 pB = *(const ulonglong2*)(prow + 2);          // pairs n0+4..n0+7
            ffma2(acc[0],  va01.x, pA.x); ffma2(acc[1],  va01.x, pA.y);
            ffma2(acc[2],  va01.x, pB.x); ffma2(acc[3],  va01.x, pB.y);
            ffma2(acc[4],  va01.y, pA.x); ffma2(acc[5],  va01.y, pA.y);
            ffma2(acc[6],  va01.y, pB.x); ffma2(acc[7],  va01.y, pB.y);
            ffma2(acc[8],  va23.x, pA.x); ffma2(acc[9],  va23.x, pA.y);
            ffma2(acc[10], va23.x, pB.x); ffma2(acc[11], va23.x, pB.y);
            ffma2(acc[12], va23.y, pA.x); ffma2(acc[13], va23.y, pA.y);
            ffma2(acc[14], va23.y, pB.x); ffma2(acc[15], va23.y, pB.y);
        }
    }

    // epilogue
#pragma unroll
    for (int i = 0; i < 4; i++) {
        float2 a0 = unpack2(acc[i * 4 + 0]);
        float2 a1 = unpack2(acc[i * 4 + 1]);
        float2 a2 = unpack2(acc[i * 4 + 2]);
        float2 a3 = unpack2(acc[i * 4 + 3]);
        float* op = out + ((size_t)(b * CC + c0 + i) << 12) + n_base + n0;
        *(float4*)(op)     = make_float4(a0.x, a0.y, a1.x, a1.y);
        *(float4*)(op + 4) = make_float4(a2.x, a2.y, a3.x, a3.y);
    }
}

// ---------------- launch ----------------
extern "C" void kernel_launch(void* const* d_in, const int* in_sizes, int n_in,
                              void* d_out, int out_size)
{
    const float* x  = (const float*)d_in[0];
    const float* Wq = (const float*)d_in[1];
    const float* bq = (const float*)d_in[2];
    const float* Wk = (const float*)d_in[3];
    const float* bk = (const float*)d_in[4];
    const float* Wv = (const float*)d_in[5];
    const float* bv = (const float*)d_in[6];
    float* out = (float*)d_out;

    cudaFuncSetAttribute(out_kernel, cudaFuncAttributeMaxDynamicSharedMemorySize, OUT_SMEM);

    proj_kernel<<<dim3(16, BATCH), 256>>>(x, Wq, bq, Wk, bk, Wv, bv);
    zr_kernel<<<dim3(32, 4, BATCH), 128>>>();
    out_kernel<<<dim3(32, BATCH), 256, OUT_SMEM>>>(out);
}

// round 4
// speedup vs baseline: 2.9807x; 2.9807x over previous
#include <cuda_runtime.h>
#include <cuda_bf16.h>
#include <cstdint>

#define BATCH 8
#define CC    64
#define DD    8
#define NPIX  4096

// ---------------- device scratch ----------------
__device__ float g_Q[BATCH * NPIX * DD];    // [b][n][d]
__device__ float g_K[BATCH * NPIX * DD];    // [b][m][d]
__device__ float g_V[BATCH * NPIX * CC];    // [b][m][c]
__device__ float g_Zp[4 * BATCH * NPIX];    // [split][b][m]

__device__ __forceinline__ uint32_t f2tf32(float f) {
    uint32_t u; asm("cvt.rna.tf32.f32 %0, %1;" : "=r"(u) : "f"(f)); return u;
}
__device__ __forceinline__ void mma_tf32(float* c, const uint32_t* a,
                                         uint32_t b0, uint32_t b1) {
    asm volatile(
        "mma.sync.aligned.m16n8k8.row.col.f32.tf32.tf32.f32 "
        "{%0,%1,%2,%3}, {%4,%5,%6,%7}, {%8,%9}, {%0,%1,%2,%3};"
        : "+f"(c[0]), "+f"(c[1]), "+f"(c[2]), "+f"(c[3])
        : "r"(a[0]), "r"(a[1]), "r"(a[2]), "r"(a[3]), "r"(b0), "r"(b1));
}

// ---------------- 1: projections (2 threads per pixel for occupancy) ----------------
__global__ void __launch_bounds__(256) proj_kernel(
    const float* __restrict__ x,
    const float* __restrict__ Wq, const float* __restrict__ bq,
    const float* __restrict__ Wk, const float* __restrict__ bk,
    const float* __restrict__ Wv, const float* __restrict__ bv)
{
    __shared__ float sWqT[CC * DD];   // [c][d]
    __shared__ float sWkT[CC * DD];
    __shared__ float sWvT[CC * CC];   // [c][d_out]
    const int tid = threadIdx.x;
    const int b = blockIdx.y;
    const int n = blockIdx.x * 128 + (tid & 127);
    const int h = tid >> 7;           // channel-half

    for (int i = tid; i < CC * DD; i += 256) {
        int d = i >> 6, c = i & 63;
        sWqT[c * DD + d] = Wq[i];
        sWkT[c * DD + d] = Wk[i];
    }
    for (int i = tid; i < CC * CC; i += 256) {
        int d = i >> 6, c = i & 63;
        sWvT[c * CC + d] = Wv[i];
    }
    __syncthreads();

    float q[DD], k[DD], v[32];
#pragma unroll
    for (int d = 0; d < DD; d++) { q[d] = 0.f; k[d] = 0.f; }
#pragma unroll
    for (int d = 0; d < 32; d++) v[d] = 0.f;

    const float* xp = x + (b * CC) * NPIX + n;
#pragma unroll 1
    for (int c = 0; c < CC; c++) {
        float xc = xp[c * NPIX];
        if (h == 0) {                 // warp-uniform branch
            const float* wq = sWqT + c * DD;
            const float* wk = sWkT + c * DD;
#pragma unroll
            for (int d = 0; d < DD; d++) {
                q[d] = fmaf(wq[d], xc, q[d]);
                k[d] = fmaf(wk[d], xc, k[d]);
            }
        }
        const float* wv = sWvT + c * CC + h * 32;
#pragma unroll
        for (int d = 0; d < 32; d++) v[d] = fmaf(wv[d], xc, v[d]);
    }

    if (h == 0) {
        float* qo = g_Q + ((b << 12) + n) * DD;
        float* ko = g_K + ((b << 12) + n) * DD;
#pragma unroll
        for (int d = 0; d < DD; d++) {
            qo[d] = q[d] + __ldg(bq + d);
            ko[d] = k[d] + __ldg(bk + d);
        }
    }
    float* vo = g_V + ((b << 12) + n) * CC + h * 32;
#pragma unroll
    for (int d = 0; d < 32; d++) vo[d] = v[d] + __ldg(bv + d + h * 32);
}

// ---------------- 2: column sums Z[m] = sum_n exp(s[n,m]) ----------------
__global__ void __launch_bounds__(128) zr_kernel()
{
    const int tid = threadIdx.x;
    const int b = blockIdx.z;
    const int ns = blockIdx.y;
    const int m = blockIdx.x * 128 + tid;

    const float4* kp = (const float4*)(g_K + ((b << 12) + m) * DD);
    const float4 ka = kp[0], kb = kp[1];

    __shared__ float4 sQ[256];
    float z0 = 0.f, z1 = 0.f;

    for (int t = 0; t < 8; t++) {
        const int nb = ns * 1024 + t * 128;
        __syncthreads();
        const float4* qg = (const float4*)(g_Q + ((b << 12) + nb) * DD);
        sQ[tid] = qg[tid];
        sQ[tid + 128] = qg[tid + 128];
        __syncthreads();
#pragma unroll 4
        for (int nl = 0; nl < 128; nl += 2) {
            float4 qa = sQ[nl * 2],     qb = sQ[nl * 2 + 1];
            float4 qc = sQ[nl * 2 + 2], qd = sQ[nl * 2 + 3];
            float s0 = ka.x*qa.x + ka.y*qa.y + ka.z*qa.z + ka.w*qa.w
                     + kb.x*qb.x + kb.y*qb.y + kb.z*qb.z + kb.w*qb.w;
            float s1 = ka.x*qc.x + ka.y*qc.y + ka.z*qc.z + ka.w*qc.w
                     + kb.x*qd.x + kb.y*qd.y + kb.z*qd.z + kb.w*qd.w;
            z0 += __expf(s0 * 0.125f);
            z1 += __expf(s1 * 0.125f);
        }
    }
    g_Zp[(ns * BATCH + b) * NPIX + m] = z0 + z1;
}

// ---------------- 3: fused PV via mma.sync tf32 ----------------
// block: 256 thr (8 warps), grid (32 n-tiles, B). C^T[n=128][c=64] in fp32 regs.
// Warp tiling: 4 warp-rows (n, 32 each) x 2 warp-cols (c, 32 each).
// smem (u32/float units): sPT[128][68] | sVB[64][72] | sQ[128][12] | sK[64*8] | sRz[64]
#define PT_STRIDE 68
#define VB_STRIDE 72
#define Q_STRIDE  12
#define OFF_PT 0
#define OFF_VB (128 * PT_STRIDE)                 // 8704
#define OFF_Q  (OFF_VB + 64 * VB_STRIDE)         // 13312
#define OFF_K  (OFF_Q + 128 * Q_STRIDE)          // 14848
#define OFF_RZ (OFF_K + 512)                     // 15360
#define OUT_SMEM ((OFF_RZ + 64) * 4)             // 61696 B

__global__ void __launch_bounds__(256, 2) out_kernel(float* __restrict__ out)
{
    extern __shared__ uint32_t sm[];
    uint32_t* sPT = sm + OFF_PT;                  // P^T tf32 [n][m-pad]
    uint32_t* sVB = sm + OFF_VB;                  // Vz tf32 [m][c-pad]
    float*    sQ  = (float*)(sm + OFF_Q);         // [n][8 + pad4]
    float*    sK  = (float*)(sm + OFF_K);         // [m][8]
    float*    sRz = (float*)(sm + OFF_RZ);        // [m]

    const int tid  = threadIdx.x;
    const int lane = tid & 31;
    const int wid  = tid >> 5;
    const int b    = blockIdx.y;
    const int n_base = blockIdx.x * 128;

    // load Q tile once: 256 float4 -> [n][12] padded rows
    {
        const float4* qg = (const float4*)(g_Q + ((b << 12) + n_base) * DD);
        float4 t = qg[tid];
        *(float4*)(sQ + (tid >> 1) * Q_STRIDE + (tid & 1) * 4) = t;
    }

    // phase-A thread mapping
    const int n_loc = tid & 127;
    const int mh = tid >> 7;            // m-half: 0 or 1 (32 m each)

    // phase-B warp mapping
    const int Mwoff = (wid & 3) * 32;   // n offset
    const int Nwoff = (wid >> 2) * 32;  // c offset
    const int g  = lane >> 2;           // groupID
    const int tg = lane & 3;            // threadID in group

    float acc[2][4][4];
#pragma unroll
    for (int i = 0; i < 2; i++)
#pragma unroll
        for (int j = 0; j < 4; j++)
#pragma unroll
            for (int r = 0; r < 4; r++) acc[i][j][r] = 0.f;

    for (int mt = 0; mt < 64; mt++) {
        const int m_base = mt * 64;
        __syncthreads();     // prev phase B done reading sPT/sVB

        // seg1: K tile + 1/Z
        if (tid < 128)
            ((float4*)sK)[tid] =
                ((const float4*)(g_K + ((b << 12) + m_base) * DD))[tid];
        if (tid < 64) {
            const int m = m_base + tid;
            float z = g_Zp[(0 * BATCH + b) * NPIX + m]
                    + g_Zp[(1 * BATCH + b) * NPIX + m]
                    + g_Zp[(2 * BATCH + b) * NPIX + m]
                    + g_Zp[(3 * BATCH + b) * NPIX + m];
            sRz[tid] = 1.0f / z;
        }
        __syncthreads();

        // seg2a: V tile * (1/Z) -> tf32 -> sVB[m][c]
        {
            const float4* vg = (const float4*)(g_V + ((b << 12) + m_base) * CC);
#pragma unroll
            for (int kk = 0; kk < 4; kk++) {
                int j = kk * 256 + tid;         // [64 m][16 float4]
                int m = j >> 4, c4 = (j & 15) * 4;
                float4 t = vg[j];
                float r = sRz[m];
                uint4 u;
                u.x = f2tf32(t.x * r); u.y = f2tf32(t.y * r);
                u.z = f2tf32(t.z * r); u.w = f2tf32(t.w * r);
                *(uint4*)(sVB + m * VB_STRIDE + c4) = u;
            }
        }

        // seg2b: phase A — scores+exp -> tf32 -> sPT[n][m]
        {
            float4 qa = *(const float4*)(sQ + n_loc * Q_STRIDE);
            float4 qb = *(const float4*)(sQ + n_loc * Q_STRIDE + 4);
            uint32_t e4[4];
#pragma unroll
            for (int mi = 0; mi < 32; mi++) {
                const int m = mh * 32 + mi;
                float4 ka = *(const float4*)(sK + m * 8);
                float4 kb = *(const float4*)(sK + m * 8 + 4);
                float s = ka.x*qa.x + ka.y*qa.y + ka.z*qa.z + ka.w*qa.w
                        + kb.x*qb.x + kb.y*qb.y + kb.z*qb.z + kb.w*qb.w;
                e4[mi & 3] = f2tf32(__expf(s * 0.125f));
                if ((mi & 3) == 3)
                    *(uint4*)(sPT + n_loc * PT_STRIDE + mh * 32 + (mi & ~3)) =
                        make_uint4(e4[0], e4[1], e4[2], e4[3]);
            }
        }
        __syncthreads();

        // phase B: C^T[n][c] += P^T[n][m] (A, row) x Vz[m][c] (B, col)
#pragma unroll
        for (int k = 0; k < 8; k++) {
            uint32_t a[2][4];
#pragma unroll
            for (int mf = 0; mf < 2; mf++) {
                const uint32_t* ap =
                    sPT + (Mwoff + mf * 16 + g) * PT_STRIDE + k * 8 + tg;
                a[mf][0] = ap[0];
                a[mf][1] = ap[8 * PT_STRIDE];
                a[mf][2] = ap[4];
                a[mf][3] = ap[8 * PT_STRIDE + 4];
            }
#pragma unroll
            for (int nf = 0; nf < 4; nf++) {
                const uint32_t* bp =
                    sVB + (k * 8 + tg) * VB_STRIDE + Nwoff + nf * 8 + g;
                uint32_t b0 = bp[0];
                uint32_t b1 = bp[4 * VB_STRIDE];
                mma_tf32(acc[0][nf], a[0], b0, b1);
                mma_tf32(acc[1][nf], a[1], b0, b1);
            }
        }
    }

    // epilogue: acc[mf][nf] -> out[b][c][n]
#pragma unroll
    for (int mf = 0; mf < 2; mf++)
#pragma unroll
        for (int nf = 0; nf < 4; nf++) {
            int n = n_base + Mwoff + mf * 16 + g;
            int c = Nwoff + nf * 8 + tg * 2;
            float* o = out + ((size_t)(b * CC + c) << 12) + n;
            o[0]        = acc[mf][nf][0];   // (c,   n)
            o[4096]     = acc[mf][nf][1];   // (c+1, n)
            o[8]        = acc[mf][nf][2];   // (c,   n+8)
            o[4096 + 8] = acc[mf][nf][3];   // (c+1, n+8)
        }
}

// ---------------- launch ----------------
extern "C" void kernel_launch(void* const* d_in, const int* in_sizes, int n_in,
                              void* d_out, int out_size)
{
    const float* x  = (const float*)d_in[0];
    const float* Wq = (const float*)d_in[1];
    const float* bq = (const float*)d_in[2];
    const float* Wk = (const float*)d_in[3];
    const float* bk = (const float*)d_in[4];
    const float* Wv = (const float*)d_in[5];
    const float* bv = (const float*)d_in[6];
    float* out = (float*)d_out;

    cudaFuncSetAttribute(out_kernel, cudaFuncAttributeMaxDynamicSharedMemorySize, OUT_SMEM);

    proj_kernel<<<dim3(32, BATCH), 256>>>(x, Wq, bq, Wk, bk, Wv, bv);
    zr_kernel<<<dim3(32, 4, BATCH), 128>>>();
    out_kernel<<<dim3(32, BATCH), 256, OUT_SMEM>>>(out);
}

// round 5
// speedup vs baseline: 4.1027x; 1.3764x over previous
#include <cuda_runtime.h>
#include <cuda_bf16.h>
#include <cstdint>

#define BATCH 8
#define CC    64
#define DD    8
#define NPIX  4096

// scale folded into K at proj time: 0.125 * log2(e)
#define KSCALE 0.18033688011112042f

// ---------------- device scratch ----------------
__device__ float g_Q[BATCH * NPIX * DD];    // [b][n][d]
__device__ float g_K[BATCH * NPIX * DD];    // [b][m][d], pre-scaled by KSCALE
__device__ float g_V[BATCH * NPIX * CC];    // [b][m][c]
__device__ float g_Zp[4 * BATCH * NPIX];    // [split][b][m]

__device__ __forceinline__ uint32_t f2tf32(float f) {
    uint32_t u; asm("cvt.rna.tf32.f32 %0, %1;" : "=r"(u) : "f"(f)); return u;
}
__device__ __forceinline__ float ex2(float x) {
    float r; asm("ex2.approx.f32 %0, %1;" : "=f"(r) : "f"(x)); return r;
}
__device__ __forceinline__ void mma_tf32(float* c, const uint32_t* a,
                                         uint32_t b0, uint32_t b1) {
    asm volatile(
        "mma.sync.aligned.m16n8k8.row.col.f32.tf32.tf32.f32 "
        "{%0,%1,%2,%3}, {%4,%5,%6,%7}, {%8,%9}, {%0,%1,%2,%3};"
        : "+f"(c[0]), "+f"(c[1]), "+f"(c[2]), "+f"(c[3])
        : "r"(a[0]), "r"(a[1]), "r"(a[2]), "r"(a[3]), "r"(b0), "r"(b1));
}
__device__ __forceinline__ uint4 cvt4(float4 t) {
    uint4 u;
    u.x = f2tf32(t.x); u.y = f2tf32(t.y); u.z = f2tf32(t.z); u.w = f2tf32(t.w);
    return u;
}

// ---------------- 1: projections (4 threads per pixel, c-unroll 4) ----------------
__global__ void __launch_bounds__(256) proj_kernel(
    const float* __restrict__ x,
    const float* __restrict__ Wq, const float* __restrict__ bq,
    const float* __restrict__ Wk, const float* __restrict__ bk,
    const float* __restrict__ Wv, const float* __restrict__ bv)
{
    __shared__ float sWqT[CC * DD];   // [c][d]
    __shared__ float sWkT[CC * DD];
    __shared__ float sWvT[CC * CC];   // [c][d_out]
    const int tid = threadIdx.x;
    const int b = blockIdx.y;
    const int n = blockIdx.x * 64 + (tid & 63);
    const int h = tid >> 6;           // channel quarter (16 each), warp-uniform

    for (int i = tid; i < CC * DD; i += 256) {
        int d = i >> 6, c = i & 63;
        sWqT[c * DD + d] = Wq[i];
        sWkT[c * DD + d] = Wk[i];
    }
    for (int i = tid; i < CC * CC; i += 256) {
        int d = i >> 6, c = i & 63;
        sWvT[c * CC + d] = Wv[i];
    }
    __syncthreads();

    float q[DD], k[DD], v[16];
#pragma unroll
    for (int d = 0; d < DD; d++) { q[d] = 0.f; k[d] = 0.f; }
#pragma unroll
    for (int d = 0; d < 16; d++) v[d] = 0.f;

    const float* xp = x + (b * CC) * NPIX + n;
#pragma unroll 1
    for (int c = 0; c < CC; c += 4) {
        float xc0 = xp[(c + 0) * NPIX];
        float xc1 = xp[(c + 1) * NPIX];
        float xc2 = xp[(c + 2) * NPIX];
        float xc3 = xp[(c + 3) * NPIX];
        if (h == 0) {
#pragma unroll
            for (int d = 0; d < DD; d++) {
                q[d] = fmaf(sWqT[(c + 0) * DD + d], xc0, q[d]);
                q[d] = fmaf(sWqT[(c + 1) * DD + d], xc1, q[d]);
                q[d] = fmaf(sWqT[(c + 2) * DD + d], xc2, q[d]);
                q[d] = fmaf(sWqT[(c + 3) * DD + d], xc3, q[d]);
                k[d] = fmaf(sWkT[(c + 0) * DD + d], xc0, k[d]);
                k[d] = fmaf(sWkT[(c + 1) * DD + d], xc1, k[d]);
                k[d] = fmaf(sWkT[(c + 2) * DD + d], xc2, k[d]);
                k[d] = fmaf(sWkT[(c + 3) * DD + d], xc3, k[d]);
            }
        }
        const float* wv = sWvT + h * 16;
#pragma unroll
        for (int d = 0; d < 16; d++) {
            v[d] = fmaf(wv[(c + 0) * CC + d], xc0, v[d]);
            v[d] = fmaf(wv[(c + 1) * CC + d], xc1, v[d]);
            v[d] = fmaf(wv[(c + 2) * CC + d], xc2, v[d]);
            v[d] = fmaf(wv[(c + 3) * CC + d], xc3, v[d]);
        }
    }

    if (h == 0) {
        float* qo = g_Q + ((b << 12) + n) * DD;
        float* ko = g_K + ((b << 12) + n) * DD;
#pragma unroll
        for (int d = 0; d < DD; d++) {
            qo[d] = q[d] + __ldg(bq + d);
            ko[d] = (k[d] + __ldg(bk + d)) * KSCALE;
        }
    }
    float* vo = g_V + ((b << 12) + n) * CC + h * 16;
#pragma unroll
    for (int d = 0; d < 16; d++) vo[d] = v[d] + __ldg(bv + d + h * 16);
}

// ---------------- 2: Z[m] = sum_n exp2(QK) via mma ----------------
// grid (64 m-tiles, 4 n-splits, B), 256 threads (8 warps).
__global__ void __launch_bounds__(256) zr_kernel()
{
    __shared__ uint32_t sK[64 * 12];     // tf32, stride 12 (conflict-free)
    __shared__ uint32_t sQ[128 * 12];
    __shared__ float    szp[8 * 64];

    const int tid  = threadIdx.x;
    const int lane = tid & 31;
    const int wid  = tid >> 5;
    const int g  = lane >> 2;
    const int tg = lane & 3;
    const int b = blockIdx.z;
    const int ns = blockIdx.y;
    const int m_base = blockIdx.x * 64;

    if (tid < 128) {
        float4 t = ((const float4*)(g_K + ((b << 12) + m_base) * DD))[tid];
        *(uint4*)(sK + (tid >> 1) * 12 + (tid & 1) * 4) = cvt4(t);
    }

    float zacc[16];
#pragma unroll
    for (int i = 0; i < 16; i++) zacc[i] = 0.f;

    for (int t = 0; t < 8; t++) {
        __syncthreads();
        {
            const int nb = ns * 1024 + t * 128;
            float4 tq = ((const float4*)(g_Q + ((b << 12) + nb) * DD))[tid];
            *(uint4*)(sQ + (tid >> 1) * 12 + (tid & 1) * 4) = cvt4(tq);
        }
        __syncthreads();

        const int nrow = wid * 16 + g;
        uint32_t a[4];
        a[0] = sQ[nrow * 12 + tg];
        a[1] = sQ[(nrow + 8) * 12 + tg];
        a[2] = sQ[nrow * 12 + tg + 4];
        a[3] = sQ[(nrow + 8) * 12 + tg + 4];

#pragma unroll
        for (int mt8 = 0; mt8 < 8; mt8++) {
            uint32_t b0 = sK[(mt8 * 8 + g) * 12 + tg];
            uint32_t b1 = sK[(mt8 * 8 + g) * 12 + tg + 4];
            float c[4] = {0.f, 0.f, 0.f, 0.f};
            mma_tf32(c, a, b0, b1);
            zacc[mt8 * 2 + 0] += ex2(c[0]) + ex2(c[2]);
            zacc[mt8 * 2 + 1] += ex2(c[1]) + ex2(c[3]);
        }
    }

    // reduce over g (lane bits 2..4)
#pragma unroll
    for (int i = 0; i < 16; i++) {
        zacc[i] += __shfl_xor_sync(0xffffffffu, zacc[i], 4);
        zacc[i] += __shfl_xor_sync(0xffffffffu, zacc[i], 8);
        zacc[i] += __shfl_xor_sync(0xffffffffu, zacc[i], 16);
    }
    if (lane < 4) {
#pragma unroll
        for (int i = 0; i < 16; i++)
            szp[wid * 64 + (i >> 1) * 8 + lane * 2 + (i & 1)] = zacc[i];
    }
    __syncthreads();
    if (tid < 64) {
        float z = 0.f;
#pragma unroll
        for (int w = 0; w < 8; w++) z += szp[w * 64 + tid];
        g_Zp[(ns * BATCH + b) * NPIX + m_base + tid] = z;
    }
}

// ---------------- 3: fused PV, all-tensor ----------------
#define PT_STRIDE 68
#define VB_STRIDE 72
#define OFF_PT 0
#define OFF_VB (128 * PT_STRIDE)                 // 8704
#define OFF_Q  (OFF_VB + 64 * VB_STRIDE)         // 13312
#define OFF_K  (OFF_Q + 128 * 12)                // 14848
#define OFF_RZ (OFF_K + 64 * 12)                 // 15616
#define OUT_SMEM ((OFF_RZ + 64) * 4)             // 62720 B

__global__ void __launch_bounds__(256, 2) out_kernel(float* __restrict__ out)
{
    extern __shared__ uint32_t sm[];
    uint32_t* sPT = sm + OFF_PT;                  // P^T tf32 [n][m], stride 68
    uint32_t* sVB = sm + OFF_VB;                  // Vz tf32 [m][c], stride 72
    uint32_t* sQ  = sm + OFF_Q;                   // tf32 [n][d], stride 12
    uint32_t* sK  = sm + OFF_K;                   // tf32 [m][d], stride 12
    float*    sRz = (float*)(sm + OFF_RZ);        // [m]

    const int tid  = threadIdx.x;
    const int lane = tid & 31;
    const int wid  = tid >> 5;
    const int b    = blockIdx.y;
    const int n_base = blockIdx.x * 128;
    const int g  = lane >> 2;
    const int tg = lane & 3;

    // load Q tile once (tf32, stride 12)
    {
        const float4* qg = (const float4*)(g_Q + ((b << 12) + n_base) * DD);
        float4 t = qg[tid];
        *(uint4*)(sQ + (tid >> 1) * 12 + (tid & 1) * 4) = cvt4(t);
    }
    __syncthreads();

    // phase-A A-fragment (constant across m-tiles)
    const int ws = wid * 16;
    uint32_t aq[4];
    aq[0] = sQ[(ws + g) * 12 + tg];
    aq[1] = sQ[(ws + g + 8) * 12 + tg];
    aq[2] = sQ[(ws + g) * 12 + tg + 4];
    aq[3] = sQ[(ws + g + 8) * 12 + tg + 4];

    // phase-B warp mapping
    const int Mwoff = (wid & 3) * 32;   // n offset
    const int Nwoff = (wid >> 2) * 32;  // c offset

    float acc[2][4][4];
#pragma unroll
    for (int i = 0; i < 2; i++)
#pragma unroll
        for (int j = 0; j < 4; j++)
#pragma unroll
            for (int r = 0; r < 4; r++) acc[i][j][r] = 0.f;

    for (int mt = 0; mt < 64; mt++) {
        const int m_base = mt * 64;
        __syncthreads();     // prev phase B done reading sPT/sVB

        // seg1: K tile (tf32) + 1/Z
        if (tid < 128) {
            float4 t = ((const float4*)(g_K + ((b << 12) + m_base) * DD))[tid];
            *(uint4*)(sK + (tid >> 1) * 12 + (tid & 1) * 4) = cvt4(t);
        }
        if (tid < 64) {
            const int m = m_base + tid;
            float z = g_Zp[(0 * BATCH + b) * NPIX + m]
                    + g_Zp[(1 * BATCH + b) * NPIX + m]
                    + g_Zp[(2 * BATCH + b) * NPIX + m]
                    + g_Zp[(3 * BATCH + b) * NPIX + m];
            sRz[tid] = 1.0f / z;
        }
        __syncthreads();

        // seg2a: V tile * (1/Z) -> tf32 -> sVB[m][c]
        {
            const float4* vg = (const float4*)(g_V + ((b << 12) + m_base) * CC);
#pragma unroll
            for (int kk = 0; kk < 4; kk++) {
                int j = kk * 256 + tid;         // [64 m][16 float4]
                int m = j >> 4, c4 = (j & 15) * 4;
                float4 t = vg[j];
                float r = sRz[m];
                t.x *= r; t.y *= r; t.z *= r; t.w *= r;
                *(uint4*)(sVB + m * VB_STRIDE + c4) = cvt4(t);
            }
        }

        // seg2b: phase A — QK mma -> ex2 -> tf32 -> sPT[n][m]
#pragma unroll
        for (int mt8 = 0; mt8 < 8; mt8++) {
            uint32_t b0 = sK[(mt8 * 8 + g) * 12 + tg];
            uint32_t b1 = sK[(mt8 * 8 + g) * 12 + tg + 4];
            float c[4] = {0.f, 0.f, 0.f, 0.f};
            mma_tf32(c, aq, b0, b1);
            uint2 lo, hi;
            lo.x = f2tf32(ex2(c[0])); lo.y = f2tf32(ex2(c[1]));
            hi.x = f2tf32(ex2(c[2])); hi.y = f2tf32(ex2(c[3]));
            *(uint2*)(sPT + (ws + g) * PT_STRIDE + mt8 * 8 + tg * 2) = lo;
            *(uint2*)(sPT + (ws + g + 8) * PT_STRIDE + mt8 * 8 + tg * 2) = hi;
        }
        __syncthreads();

        // phase B: C^T[n][c] += P^T[n][m] x Vz[m][c]
#pragma unroll
        for (int k = 0; k < 8; k++) {
            uint32_t a[2][4];
#pragma unroll
            for (int mf = 0; mf < 2; mf++) {
                const uint32_t* ap =
                    sPT + (Mwoff + mf * 16 + g) * PT_STRIDE + k * 8 + tg;
                a[mf][0] = ap[0];
                a[mf][1] = ap[8 * PT_STRIDE];
                a[mf][2] = ap[4];
                a[mf][3] = ap[8 * PT_STRIDE + 4];
            }
#pragma unroll
            for (int nf = 0; nf < 4; nf++) {
                const uint32_t* bp =
                    sVB + (k * 8 + tg) * VB_STRIDE + Nwoff + nf * 8 + g;
                uint32_t b0 = bp[0];
                uint32_t b1 = bp[4 * VB_STRIDE];
                mma_tf32(acc[0][nf], a[0], b0, b1);
                mma_tf32(acc[1][nf], a[1], b0, b1);
            }
        }
    }

    // epilogue: acc[mf][nf] -> out[b][c][n]
#pragma unroll
    for (int mf = 0; mf < 2; mf++)
#pragma unroll
        for (int nf = 0; nf < 4; nf++) {
            int n = n_base + Mwoff + mf * 16 + g;
            int c = Nwoff + nf * 8 + tg * 2;
            float* o = out + ((size_t)(b * CC + c) << 12) + n;
            o[0]        = acc[mf][nf][0];
            o[4096]     = acc[mf][nf][1];
            o[8]        = acc[mf][nf][2];
            o[4096 + 8] = acc[mf][nf][3];
        }
}

// ---------------- launch ----------------
extern "C" void kernel_launch(void* const* d_in, const int* in_sizes, int n_in,
                              void* d_out, int out_size)
{
    const float* x  = (const float*)d_in[0];
    const float* Wq = (const float*)d_in[1];
    const float* bq = (const float*)d_in[2];
    const float* Wk = (const float*)d_in[3];
    const float* bk = (const float*)d_in[4];
    const float* Wv = (const float*)d_in[5];
    const float* bv = (const float*)d_in[6];
    float* out = (float*)d_out;

    cudaFuncSetAttribute(out_kernel, cudaFuncAttributeMaxDynamicSharedMemorySize, OUT_SMEM);

    proj_kernel<<<dim3(64, BATCH), 256>>>(x, Wq, bq, Wk, bk, Wv, bv);
    zr_kernel<<<dim3(64, 4, BATCH), 256>>>();
    out_kernel<<<dim3(32, BATCH), 256, OUT_SMEM>>>(out);
}

// round 7
// speedup vs baseline: 6.4619x; 1.5750x over previous
#include <cuda_runtime.h>
#include <cuda_bf16.h>
#include <cstdint>

#define BATCH 8
#define CC    64
#define DD    8
#define NPIX  4096

// 0.125 * log2(e), folded into K at proj time
#define KSCALE 0.18033688011112042f

// ---------------- device scratch ----------------
__device__ float         g_Q[BATCH * NPIX * DD];   // [b][n][d] fp32
__device__ float         g_K[BATCH * NPIX * DD];   // [b][m][d] fp32, pre-scaled
__device__ __nv_bfloat16 g_Vbf[BATCH * CC * NPIX]; // [b][c][m] bf16
__device__ float         g_Zp[4 * BATCH * NPIX];   // [split][b][m]
__device__ float         g_Rz[BATCH * NPIX];       // [b][m] 1/Z
__device__ float         g_y[BATCH * CC];          // [b][c] = sum_m x[c,m]*rz[m]
__device__ float         g_O0[BATCH * CC];         // [b][c] term-1 output

__device__ __forceinline__ uint32_t f2tf32(float f) {
    uint32_t u; asm("cvt.rna.tf32.f32 %0, %1;" : "=r"(u) : "f"(f)); return u;
}
__device__ __forceinline__ float ex2(float x) {
    float r; asm("ex2.approx.f32 %0, %1;" : "=f"(r) : "f"(x)); return r;
}
__device__ __forceinline__ uint32_t bf2(float lo, float hi) {
    // pack: low half = lo, high half = hi
    uint32_t r; asm("cvt.rn.bf16x2.f32 %0, %1, %2;" : "=r"(r) : "f"(hi), "f"(lo));
    return r;
}
__device__ __forceinline__ uint4 cvt4(float4 t) {
    uint4 u;
    u.x = f2tf32(t.x); u.y = f2tf32(t.y); u.z = f2tf32(t.z); u.w = f2tf32(t.w);
    return u;
}
__device__ __forceinline__ void mma_tf32(float* c, const uint32_t* a,
                                         uint32_t b0, uint32_t b1) {
    asm volatile(
        "mma.sync.aligned.m16n8k8.row.col.f32.tf32.tf32.f32 "
        "{%0,%1,%2,%3}, {%4,%5,%6,%7}, {%8,%9}, {%0,%1,%2,%3};"
        : "+f"(c[0]), "+f"(c[1]), "+f"(c[2]), "+f"(c[3])
        : "r"(a[0]), "r"(a[1]), "r"(a[2]), "r"(a[3]), "r"(b0), "r"(b1));
}
__device__ __forceinline__ void mma_bf16(float* c, const uint32_t* a,
                                         uint32_t b0, uint32_t b1) {
    asm volatile(
        "mma.sync.aligned.m16n8k16.row.col.f32.bf16.bf16.f32 "
        "{%0,%1,%2,%3}, {%4,%5,%6,%7}, {%8,%9}, {%0,%1,%2,%3};"
        : "+f"(c[0]), "+f"(c[1]), "+f"(c[2]), "+f"(c[3])
        : "r"(a[0]), "r"(a[1]), "r"(a[2]), "r"(a[3]), "r"(b0), "r"(b1));
}
__device__ __forceinline__ void cp_async16(uint32_t dst, const void* src) {
    asm volatile("cp.async.ca.shared.global [%0], [%1], 16;"
                 :: "r"(dst), "l"(src));
}

// ---------------- 1: projections, unified 80-channel weights ----------------
__global__ void __launch_bounds__(256) proj_kernel(
    const float* __restrict__ x,
    const float* __restrict__ Wq, const float* __restrict__ bq,
    const float* __restrict__ Wk, const float* __restrict__ bk,
    const float* __restrict__ Wv, const float* __restrict__ bv)
{
    __shared__ float sW[CC * 80];   // [c][j]  j: 0-7 q, 8-15 k(scaled), 16-79 v
    __shared__ float sB[80];
    const int tid = threadIdx.x;
    const int b = blockIdx.y;
    const int s = tid & 63;
    const int h = tid >> 6;
    const int ch0 = h * 20;

    for (int i = tid; i < CC * 80; i += 256) {
        int c = i / 80, j = i % 80;
        float w;
        if (j < 8)       w = Wq[j * CC + c];
        else if (j < 16) w = Wk[(j - 8) * CC + c] * KSCALE;
        else             w = Wv[(j - 16) * CC + c];
        sW[c * 80 + j] = w;
    }
    if (tid < 80) {
        float bb;
        if (tid < 8)       bb = bq[tid];
        else if (tid < 16) bb = bk[tid - 8] * KSCALE;
        else               bb = bv[tid - 16];
        sB[tid] = bb;
    }
    __syncthreads();

    float a[4][20];
#pragma unroll
    for (int p = 0; p < 4; p++)
#pragma unroll
        for (int j = 0; j < 20; j++) a[p][j] = 0.f;

    const int nb = blockIdx.x * 256 + s;
    const float* xb = x + ((size_t)b * CC << 12) + nb;
#pragma unroll 1
    for (int c = 0; c < CC; c += 2) {
        float x0[4], x1[4];
#pragma unroll
        for (int p = 0; p < 4; p++) {
            x0[p] = xb[((size_t)c << 12) + p * 64];
            x1[p] = xb[((size_t)(c + 1) << 12) + p * 64];
        }
        const float* w0 = sW + c * 80 + ch0;
        const float* w1 = sW + (c + 1) * 80 + ch0;
#pragma unroll
        for (int j = 0; j < 20; j++) {
            float ww0 = w0[j], ww1 = w1[j];
#pragma unroll
            for (int p = 0; p < 4; p++) {
                a[p][j] = fmaf(ww0, x0[p], a[p][j]);
                a[p][j] = fmaf(ww1, x1[p], a[p][j]);
            }
        }
    }

#pragma unroll
    for (int p = 0; p < 4; p++) {
        const int n = nb + p * 64;
        if (h == 0) {
            float4 q0 = make_float4(a[p][0] + sB[0], a[p][1] + sB[1],
                                    a[p][2] + sB[2], a[p][3] + sB[3]);
            float4 q1 = make_float4(a[p][4] + sB[4], a[p][5] + sB[5],
                                    a[p][6] + sB[6], a[p][7] + sB[7]);
            float4 k0 = make_float4(a[p][8] + sB[8], a[p][9] + sB[9],
                                    a[p][10] + sB[10], a[p][11] + sB[11]);
            float4 k1 = make_float4(a[p][12] + sB[12], a[p][13] + sB[13],
                                    a[p][14] + sB[14], a[p][15] + sB[15]);
            float4* qo = (float4*)(g_Q + ((b << 12) + n) * DD);
            qo[0] = q0; qo[1] = q1;
            float4* ko = (float4*)(g_K + ((b << 12) + n) * DD);
            ko[0] = k0; ko[1] = k1;
#pragma unroll
            for (int j = 16; j < 20; j++)
                g_Vbf[(((size_t)b * CC + (j - 16)) << 12) + n] =
                    __float2bfloat16(a[p][j] + sB[j]);
        } else {
#pragma unroll
            for (int j = 0; j < 20; j++) {
                int ch = ch0 - 16 + j;   // V channel for accumulator a[p][j]
                g_Vbf[(((size_t)b * CC + ch) << 12) + n] =
                    __float2bfloat16(a[p][j] + sB[ch0 + j]);   // FIX R6: was a[p][ch0+j] (OOB)
            }
        }
    }
}

// ---------------- 2: Z[m] = sum_n exp2(QK) via mma ----------------
__global__ void __launch_bounds__(256) zr_kernel()
{
    __shared__ uint32_t sK[64 * 12];
    __shared__ uint32_t sQ[128 * 12];
    __shared__ float    szp[8 * 64];

    const int tid  = threadIdx.x;
    const int lane = tid & 31;
    const int wid  = tid >> 5;
    const int g  = lane >> 2;
    const int tg = lane & 3;
    const int b = blockIdx.z;
    const int ns = blockIdx.y;
    const int m_base = blockIdx.x * 64;

    if (tid < 128) {
        float4 t = ((const float4*)(g_K + ((b << 12) + m_base) * DD))[tid];
        *(uint4*)(sK + (tid >> 1) * 12 + (tid & 1) * 4) = cvt4(t);
    }

    float zacc[16];
#pragma unroll
    for (int i = 0; i < 16; i++) zacc[i] = 0.f;

    for (int t = 0; t < 8; t++) {
        __syncthreads();
        {
            const int nb = ns * 1024 + t * 128;
            float4 tq = ((const float4*)(g_Q + ((b << 12) + nb) * DD))[tid];
            *(uint4*)(sQ + (tid >> 1) * 12 + (tid & 1) * 4) = cvt4(tq);
        }
        __syncthreads();

        const int nrow = wid * 16 + g;
        uint32_t a[4];
        a[0] = sQ[nrow * 12 + tg];
        a[1] = sQ[(nrow + 8) * 12 + tg];
        a[2] = sQ[nrow * 12 + tg + 4];
        a[3] = sQ[(nrow + 8) * 12 + tg + 4];

#pragma unroll
        for (int mt8 = 0; mt8 < 8; mt8++) {
            uint32_t b0 = sK[(mt8 * 8 + g) * 12 + tg];
            uint32_t b1 = sK[(mt8 * 8 + g) * 12 + tg + 4];
            float c[4] = {0.f, 0.f, 0.f, 0.f};
            mma_tf32(c, a, b0, b1);
            zacc[mt8 * 2 + 0] += ex2(c[0]) + ex2(c[2]);
            zacc[mt8 * 2 + 1] += ex2(c[1]) + ex2(c[3]);
        }
    }

#pragma unroll
    for (int i = 0; i < 16; i++) {
        zacc[i] += __shfl_xor_sync(0xffffffffu, zacc[i], 4);
        zacc[i] += __shfl_xor_sync(0xffffffffu, zacc[i], 8);
        zacc[i] += __shfl_xor_sync(0xffffffffu, zacc[i], 16);
    }
    if (lane < 4) {
#pragma unroll
        for (int i = 0; i < 16; i++)
            szp[wid * 64 + (i >> 1) * 8 + lane * 2 + (i & 1)] = zacc[i];
    }
    __syncthreads();
    if (tid < 64) {
        float z = 0.f;
#pragma unroll
        for (int w = 0; w < 8; w++) z += szp[w * 64 + tid];
        g_Zp[(ns * BATCH + b) * NPIX + m_base + tid] = z;
    }
}

// ---------------- 2b: Rz = 1/sum(Zp) ----------------
__global__ void __launch_bounds__(256) rza_kernel()
{
    int i = blockIdx.x * 256 + threadIdx.x;   // 32768
    int b = i >> 12, m = i & 4095;
    float z = g_Zp[(0 * BATCH + b) * NPIX + m]
            + g_Zp[(1 * BATCH + b) * NPIX + m]
            + g_Zp[(2 * BATCH + b) * NPIX + m]
            + g_Zp[(3 * BATCH + b) * NPIX + m];
    g_Rz[i] = 1.0f / z;
}

// ---------------- 2c: y[b][c] = sum_m x[b][c][m] * rz[b][m] ----------------
__global__ void __launch_bounds__(128) o0a_kernel(const float* __restrict__ x)
{
    __shared__ float red[128];
    const int c = blockIdx.x, b = blockIdx.y, tid = threadIdx.x;
    const float* xp = x + (((size_t)b * CC + c) << 12);
    const float* rz = g_Rz + (b << 12);
    float acc = 0.f;
    for (int m = tid; m < NPIX; m += 128)
        acc = fmaf(xp[m], rz[m], acc);
    red[tid] = acc;
    __syncthreads();
    for (int s = 64; s; s >>= 1) {
        if (tid < s) red[tid] += red[tid + s];
        __syncthreads();
    }
    if (tid == 0) g_y[b * CC + c] = red[0];
}

// ---------------- 2d: O0[b][d] = Wv.y + bv*sum(rz) ----------------
__global__ void __launch_bounds__(64) o0b_kernel(
    const float* __restrict__ Wv, const float* __restrict__ bv)
{
    __shared__ float sred[64];
    __shared__ float sy[64];
    const int b = blockIdx.x, tid = threadIdx.x;
    const float* rz = g_Rz + (b << 12);
    float s = 0.f;
    for (int m = tid; m < NPIX; m += 64) s += rz[m];
    sred[tid] = s;
    sy[tid] = g_y[b * CC + tid];
    __syncthreads();
    for (int k = 32; k; k >>= 1) {
        if (tid < k) sred[tid] += sred[tid + k];
        __syncthreads();
    }
    float S = sred[0];
    float acc = bv[tid] * S;
    for (int c = 0; c < CC; c++)
        acc = fmaf(Wv[tid * CC + c], sy[c], acc);
    g_O0[b * CC + tid] = acc;
}

// ---------------- 3: term2 out2 = sum_m Vbf[c,m] * (exp2(s)-1)*rz[m] ----------------
#define OFF_PBF 0                       // sPbf  u32 [128][36]  = 4608
#define OFF_VB0 4608                    // sVbf0 u32 [64][36]   = 2304
#define OFF_VB1 6912                    // sVbf1
#define OFF_Q   9216                    // sQ tf32 [128][12]    = 1536
#define OFF_K   10752                   // sK tf32 [64][12]     = 768
#define OFF_RZ  11520                   // sRz f32 [64]
#define OUT_SMEM ((11520 + 64) * 4)     // 46336 B

__global__ void __launch_bounds__(256, 2) out_kernel(float* __restrict__ out)
{
    extern __shared__ uint32_t sm[];
    uint32_t* sPbf = sm + OFF_PBF;      // delta' bf16 pairs [n][m/2], stride 36
    uint32_t* sQ   = sm + OFF_Q;
    uint32_t* sK   = sm + OFF_K;
    float*    sRz  = (float*)(sm + OFF_RZ);

    const int tid  = threadIdx.x;
    const int lane = tid & 31;
    const int wid  = tid >> 5;
    const int b    = blockIdx.y;
    const int n_base = blockIdx.x * 128;
    const int g  = lane >> 2;
    const int tg = lane & 3;

    // Q tile once
    {
        const float4* qg = (const float4*)(g_Q + ((b << 12) + n_base) * DD);
        float4 t = qg[tid];
        *(uint4*)(sQ + (tid >> 1) * 12 + (tid & 1) * 4) = cvt4(t);
    }
    __syncthreads();

    const int ws = wid * 16;            // phase-A n rows
    uint32_t aq[4];
    aq[0] = sQ[(ws + g) * 12 + tg];
    aq[1] = sQ[(ws + g + 8) * 12 + tg];
    aq[2] = sQ[(ws + g) * 12 + tg + 4];
    aq[3] = sQ[(ws + g + 8) * 12 + tg + 4];

    // phase-B warp mapping: 4 n-rows x 2 m-halves, c full
    const int Mwoff = (wid & 3) * 32;
    const int mh    = wid >> 2;

    float acc[64];
#pragma unroll
    for (int i = 0; i < 64; i++) acc[i] = 0.f;

    // prefetch tile 0
    float4 vK; float vRz = 0.f;
    if (tid < 128) vK = ((const float4*)(g_K + (b << 12) * DD))[tid];
    if (tid < 64)  vRz = g_Rz[(b << 12) + tid];
    {   // cp.async V tile 0 -> buf0
        const char* src = (const char*)(g_Vbf + ((size_t)b * CC << 12));
#pragma unroll
        for (int k = 0; k < 2; k++) {
            int q = tid + k * 256;          // 512 chunks of 16B
            int row = q >> 3, off = (q & 7) * 16;
            uint32_t dst = (uint32_t)__cvta_generic_to_shared(
                (char*)(sm + OFF_VB0) + row * 144 + off);
            cp_async16(dst, src + ((size_t)row << 13) + off);
        }
        asm volatile("cp.async.commit_group;");
    }

    for (int mt = 0; mt < 64; mt++) {
        const int par = mt & 1;
        uint32_t* sVb = sm + (par ? OFF_VB1 : OFF_VB0);
        __syncthreads();                        // S1

        // store prefetched K (tf32) + rz
        if (tid < 128)
            *(uint4*)(sK + (tid >> 1) * 12 + (tid & 1) * 4) = cvt4(vK);
        if (tid < 64) sRz[tid] = vRz;

        // reg-prefetch next K/rz
        if (mt < 63) {
            const int mb2 = (mt + 1) * 64;
            if (tid < 128)
                vK = ((const float4*)(g_K + ((b << 12) + mb2) * DD))[tid];
            if (tid < 64) vRz = g_Rz[(b << 12) + mb2 + tid];
        }
        asm volatile("cp.async.wait_group 0;"); // V tile mt ready
        __syncthreads();                        // S2

        // phase A: QK mma -> delta' = (ex2(s)-1)*rz -> bf16 pairs
#pragma unroll
        for (int mt8 = 0; mt8 < 8; mt8++) {
            uint32_t b0 = sK[(mt8 * 8 + g) * 12 + tg];
            uint32_t b1 = sK[(mt8 * 8 + g) * 12 + tg + 4];
            float c[4] = {0.f, 0.f, 0.f, 0.f};
            mma_tf32(c, aq, b0, b1);
            float2 rr = *(const float2*)(sRz + mt8 * 8 + tg * 2);
            float d0 = fmaf(ex2(c[0]), rr.x, -rr.x);
            float d1 = fmaf(ex2(c[1]), rr.y, -rr.y);
            float d2 = fmaf(ex2(c[2]), rr.x, -rr.x);
            float d3 = fmaf(ex2(c[3]), rr.y, -rr.y);
            sPbf[(ws + g) * 36 + mt8 * 4 + tg]     = bf2(d0, d1);
            sPbf[(ws + g + 8) * 36 + mt8 * 4 + tg] = bf2(d2, d3);
        }

        // issue cp.async for next V tile into other buffer
        if (mt < 63) {
            const char* src = (const char*)(g_Vbf + ((size_t)b * CC << 12))
                            + (mt + 1) * 64 * 2;
            uint32_t* dbuf = sm + (par ? OFF_VB0 : OFF_VB1);
#pragma unroll
            for (int k = 0; k < 2; k++) {
                int q = tid + k * 256;
                int row = q >> 3, off = (q & 7) * 16;
                uint32_t dst = (uint32_t)__cvta_generic_to_shared(
                    (char*)dbuf + row * 144 + off);
                cp_async16(dst, src + ((size_t)row << 13) + off);
            }
            asm volatile("cp.async.commit_group;");
        }
        __syncthreads();                        // S3

        // phase B: bf16 mma, warp covers 32n x 64c x 32m (m-half mh)
#pragma unroll
        for (int ks = 0; ks < 2; ks++) {
            const int colb = mh * 16 + ks * 8 + tg;
            uint32_t a[2][4];
#pragma unroll
            for (int mf = 0; mf < 2; mf++) {
                const uint32_t* ap = sPbf + (Mwoff + mf * 16 + g) * 36 + colb;
                a[mf][0] = ap[0];
                a[mf][1] = ap[8 * 36];
                a[mf][2] = ap[4];
                a[mf][3] = ap[8 * 36 + 4];
            }
#pragma unroll
            for (int nf = 0; nf < 8; nf++) {
                const uint32_t* bp = sVb + (nf * 8 + g) * 36 + colb;
                uint32_t b0 = bp[0], b1 = bp[4];
                mma_bf16(acc + 0 * 32 + nf * 4, a[0], b0, b1);
                mma_bf16(acc + 1 * 32 + nf * 4, a[1], b0, b1);
            }
        }
    }

    // epilogue: reduce m-halves across warp pairs, add O0, store
    __syncthreads();
    float* sred = (float*)sm;           // 4 * 2176 floats
    if (wid >= 4) {
        float* dst = sred + (wid - 4) * 2176 + lane * 68;
#pragma unroll
        for (int i = 0; i < 64; i++) dst[i] = acc[i];
    }
    __syncthreads();
    if (wid < 4) {
        const float* src = sred + wid * 2176 + lane * 68;
#pragma unroll
        for (int i = 0; i < 64; i++) acc[i] += src[i];
#pragma unroll
        for (int mf = 0; mf < 2; mf++)
#pragma unroll
            for (int nf = 0; nf < 8; nf++) {
                int n = n_base + Mwoff + mf * 16 + g;
                int c = nf * 8 + tg * 2;
                float o0a_ = __ldg(g_O0 + b * CC + c);
                float o0b_ = __ldg(g_O0 + b * CC + c + 1);
                float* o = out + (((size_t)b * CC + c) << 12) + n;
                const float* ac = acc + mf * 32 + nf * 4;
                o[0]        = ac[0] + o0a_;
                o[4096]     = ac[1] + o0b_;
                o[8]        = ac[2] + o0a_;
                o[4096 + 8] = ac[3] + o0b_;
            }
    }
}

// ---------------- launch ----------------
extern "C" void kernel_launch(void* const* d_in, const int* in_sizes, int n_in,
                              void* d_out, int out_size)
{
    const float* x  = (const float*)d_in[0];
    const float* Wq = (const float*)d_in[1];
    const float* bq = (const float*)d_in[2];
    const float* Wk = (const float*)d_in[3];
    const float* bk = (const float*)d_in[4];
    const float* Wv = (const float*)d_in[5];
    const float* bv = (const float*)d_in[6];
    float* out = (float*)d_out;

    cudaFuncSetAttribute(out_kernel, cudaFuncAttributeMaxDynamicSharedMemorySize, OUT_SMEM);

    proj_kernel<<<dim3(16, BATCH), 256>>>(x, Wq, bq, Wk, bk, Wv, bv);
    zr_kernel<<<dim3(64, 4, BATCH), 256>>>();
    rza_kernel<<<128, 256>>>();
    o0a_kernel<<<dim3(CC, BATCH), 128>>>(x);
    o0b_kernel<<<BATCH, 64>>>(Wv, bv);
    out_kernel<<<dim3(32, BATCH), 256, OUT_SMEM>>>(out);
}